// round 13
// baseline (speedup 1.0000x reference)
#include <cuda_runtime.h>
#include <cuda_bf16.h>
#include <math.h>
#include <stdint.h>

#define Tc   336
#define BNT  16384
#define Fc   720
#define Nch  128
#define Bc   128
#define KC   48          // k-cols per smem stage
#define NSTG 7           // 336/48
#define RSTR 112         // smem row stride bytes (48 bf16 = 96B + 16 pad; 112/16=7 coprime 8)
#define NTHR 512

// ---------------- scratch globals ----------------
__device__ float g_ms[BNT*8];
__device__ float g_spmu[BNT*4];
__device__ float g_spsg[BNT*4];
__device__ float g_w[BNT*4];
__device__ float g_coef[BNT*8];
__device__ float g_S[64 + 4*Fc];

// pre-split bf16 planes
#define NEPS (BNT*4*Tc)           // 22,020,096
#define NX   (BNT*Tc)             // 5,505,024
#define W1ROWS 3072               // wg 0..63 | fitters 64..2943 | mu 2944..3007 | sg 3008..3071
#define NW1  (W1ROWS*Tc)
__device__ __nv_bfloat16 g_eh[NEPS];
__device__ __nv_bfloat16 g_el[NEPS];
__device__ __nv_bfloat16 g_xh[NX];
__device__ __nv_bfloat16 g_xl[NX];
__device__ __nv_bfloat16 g_wh[NW1];
__device__ __nv_bfloat16 g_wl[NW1];

__device__ __forceinline__ float softplus_f(float x){
    return fmaxf(x,0.f) + log1pf(expf(-fabsf(x)));
}
__device__ __forceinline__ uint32_t su32(const void* p){
    uint32_t a;
    asm("{ .reg .u64 t; cvta.to.shared.u64 t, %1; cvt.u32.u64 %0, t; }" : "=r"(a) : "l"(p));
    return a;
}

#define LDSM4(r, a) asm volatile( \
    "ldmatrix.sync.aligned.m8n8.x4.shared.b16 {%0,%1,%2,%3}, [%4];" \
    : "=r"((r)[0]), "=r"((r)[1]), "=r"((r)[2]), "=r"((r)[3]) : "r"(a))
#define MMA(c, a, b) asm volatile( \
    "mma.sync.aligned.m16n8k16.row.col.f32.bf16.bf16.f32 " \
    "{%0,%1,%2,%3}, {%4,%5,%6,%7}, {%8,%9}, {%0,%1,%2,%3};" \
    : "+f"((c)[0]), "+f"((c)[1]), "+f"((c)[2]), "+f"((c)[3]) \
    : "r"((a)[0]), "r"((a)[1]), "r"((a)[2]), "r"((a)[3]), "r"((b)[0]), "r"((b)[1]))

__device__ __forceinline__ void cp16(uint32_t dst, const void* src, bool pred){
    int sz = pred ? 16 : 0;
    asm volatile("cp.async.cg.shared.global [%0], [%1], 16, %2;"
                 :: "r"(dst), "l"(src), "r"(sz) : "memory");
}
#define CP_COMMIT() asm volatile("cp.async.commit_group;" ::: "memory")
template<int N> __device__ __forceinline__ void cp_wait(){
    asm volatile("cp.async.wait_group %0;" :: "n"(N) : "memory");
}

__device__ __forceinline__ void cvt_split(float4 v, uint2& h, uint2& lo){
    __nv_bfloat162 h01 = __floats2bfloat162_rn(v.x, v.y);
    __nv_bfloat162 h23 = __floats2bfloat162_rn(v.z, v.w);
    float2 f01 = __bfloat1622float2(h01), f23 = __bfloat1622float2(h23);
    __nv_bfloat162 l01 = __floats2bfloat162_rn(v.x - f01.x, v.y - f01.y);
    __nv_bfloat162 l23 = __floats2bfloat162_rn(v.z - f23.x, v.w - f23.y);
    h  = make_uint2(*(uint32_t*)&h01, *(uint32_t*)&h23);
    lo = make_uint2(*(uint32_t*)&l01, *(uint32_t*)&l23);
}

// =====================================================================
// 512-thread cp.async 3-stage split-bf16 mma.sync GEMM + fused epilogue.
//   acc[m,n] = A[m,:].W1[n,:]  (K=336, hi/lo bf16 planes pre-split)
//   h = relu(b1[n] + smu[m]*S[n] + ssg[m]*acc)
//   WMODE 0: out[m*ostride+ooff+d] = sum_n h*W2[d,n]
//   WMODE 1: logits -> softmax over groups of 4 rows -> out (g_w)
// =====================================================================
template<int NTILE, int RT, int WMODE>
__device__ __forceinline__ void gemm_core(
    const __nv_bfloat16* __restrict__ Ah, const __nv_bfloat16* __restrict__ Al, int lda,
    const __nv_bfloat16* __restrict__ Wh, const __nv_bfloat16* __restrict__ Wl, int Ncols, int n_nt,
    const float* __restrict__ b1, const float* __restrict__ S,
    const float* __restrict__ spmu, const float* __restrict__ spsg,
    int sp_mul, int sp_add,
    const float* __restrict__ W2, int R,
    float* __restrict__ outp, int ostride, int ooff,
    int m0, char* smem)
{
    constexpr int AHALF = 128*RSTR;            // 14336
    constexpr int BHALF = NTILE*RSTR;
    constexpr int BUFSZ = 2*AHALF + 2*BHALF;
    constexpr int TOTC  = 128*12 + NTILE*12;   // 16B chunks per stage
    constexpr int NIT   = (TOTC + NTHR - 1)/NTHR;
    constexpr bool CGUARD = (TOTC % NTHR) != 0;
    constexpr int NJ    = NTILE/32;            // n8 tiles per warp (4x4 grid)
    constexpr int NPW   = NTILE/4;             // N cols per warp

    const int tid = threadIdx.x;
    const int wid = tid >> 5, lane = tid & 31;
    const int g = lane >> 2, l = lane & 3;
    const int wm = wid >> 2, wn = wid & 3;     // 4x4 warp grid
    const uint32_t sb = su32(smem);
    float* stg = (float*)(smem + 3*BUFSZ);
    float* red = (float*)(smem + 3*BUFSZ + (2+RT)*NTILE*4);

    if (tid < 128) ((float4*)red)[tid] = make_float4(0.f,0.f,0.f,0.f);

    float part[4][RT];
    #pragma unroll
    for (int s = 0; s < 4; s++)
        #pragma unroll
        for (int d = 0; d < RT; d++) part[s][d] = 0.f;

    // issue cp.async for one k-stage into ring buffer kc%3
    auto issue = [&](int nt, int kc){
        char* bb = smem + (kc % 3)*BUFSZ;
        const int koff = kc*KC;
        #pragma unroll
        for (int it = 0; it < NIT; it++){
            int q = tid + it*NTHR;
            if (CGUARD && q >= TOTC) break;
            if (q < 1536){   // A planes
                int half = (q >= 768);
                int w = q - half*768;
                int r = w/6, cq = w - r*6;
                const __nv_bfloat16* src = (half ? Al : Ah) + (long)(m0 + r)*lda + koff + cq*8;
                uint32_t dst = sb + (kc%3)*BUFSZ + half*AHALF + r*RSTR + cq*16;
                cp16(dst, src, true);
            } else {         // B planes
                int w = q - 1536;
                int half = (w >= NTILE*6);
                w -= half*NTILE*6;
                int n = w/6, cq = w - n*6;
                int gn = nt*NTILE + n;
                const __nv_bfloat16* src = (half ? Wl : Wh) + (long)gn*Tc + koff + cq*8;
                uint32_t dst = sb + (kc%3)*BUFSZ + 2*AHALF + half*BHALF + n*RSTR + cq*16;
                cp16(dst, src, gn < Ncols);
            }
        }
        (void)bb;
    };

    for (int nt = 0; nt < n_nt; nt++){
        __syncthreads();   // stg + ring buffer reuse safety
        // staging: b1 / S / W2 rows for this n-tile
        for (int idx = tid; idx < NTILE*(2+RT); idx += NTHR){
            int n = idx % NTILE, row = idx / NTILE;
            int gn = nt*NTILE + n;
            float v = 0.f;
            if (gn < Ncols){
                if (row == 0)           v = b1[gn];
                else if (row == 1)      v = (S != nullptr) ? S[gn] : 0.f;
                else if (row - 2 < R)   v = W2[(row-2)*Ncols + gn];
            }
            stg[row*NTILE + n] = v;
        }

        float acc[2][NJ][4];
        #pragma unroll
        for (int i = 0; i < 2; i++)
            #pragma unroll
            for (int j = 0; j < NJ; j++)
                #pragma unroll
                for (int e = 0; e < 4; e++) acc[i][j][e] = 0.f;

        issue(nt, 0); CP_COMMIT();
        issue(nt, 1); CP_COMMIT();

        // one MMA k-step (k16) over the given buffer
        auto mma_step = [&](uint32_t base, int ks){
            uint32_t ah[2][4], al[2][4];
            #pragma unroll
            for (int i = 0; i < 2; i++){
                int row = wm*32 + i*16 + (lane & 15);
                uint32_t ad = base + row*RSTR + ks*32 + ((lane>>4)<<4);
                LDSM4(ah[i], ad);
                LDSM4(al[i], ad + AHALF);
            }
            uint32_t bh[NJ][2], bl[NJ][2];
            #pragma unroll
            for (int p = 0; p < NJ/2; p++){
                int rowb = wn*NPW + p*16 + ((lane>>4)<<3) + (lane & 7);
                uint32_t ad = base + 2*AHALF + rowb*RSTR + ks*32 + (((lane>>3)&1)<<4);
                uint32_t t[4];
                LDSM4(t, ad);
                bh[2*p][0]=t[0]; bh[2*p][1]=t[1]; bh[2*p+1][0]=t[2]; bh[2*p+1][1]=t[3];
                LDSM4(t, ad + BHALF);
                bl[2*p][0]=t[0]; bl[2*p][1]=t[1]; bl[2*p+1][0]=t[2]; bl[2*p+1][1]=t[3];
            }
            #pragma unroll
            for (int i = 0; i < 2; i++)
                #pragma unroll
                for (int j = 0; j < NJ; j++){
                    MMA(acc[i][j], ah[i], bh[j]);
                    MMA(acc[i][j], ah[i], bl[j]);
                    MMA(acc[i][j], al[i], bh[j]);
                }
        };

        for (int kc = 0; kc < NSTG; kc++){
            if (kc == NSTG-1) cp_wait<0>(); else cp_wait<1>();
            __syncthreads();
            if (kc + 2 < NSTG){ issue(nt, kc+2); CP_COMMIT(); }
            const uint32_t base = sb + (kc % 3)*BUFSZ;
            mma_step(base, 0);
            mma_step(base, 1);
            mma_step(base, 2);
        }

        // ---- epilogue: relu + affine + partial n-reduction ----
        float smu4[4], ssg4[4];
        #pragma unroll
        for (int s = 0; s < 4; s++){
            if (spmu != nullptr){
                int row = m0 + wm*32 + (s>>1)*16 + g + (s&1)*8;
                smu4[s] = spmu[row*sp_mul + sp_add];
                ssg4[s] = spsg[row*sp_mul + sp_add];
            } else { smu4[s] = 0.f; ssg4[s] = 1.f; }
        }
        #pragma unroll
        for (int i = 0; i < 2; i++)
            #pragma unroll
            for (int j = 0; j < NJ; j++)
                #pragma unroll
                for (int e = 0; e < 4; e++){
                    int nl = wn*NPW + j*8 + 2*l + (e&1);
                    int s  = i*2 + (e>>1);
                    float hv = fmaxf(stg[nl] + smu4[s]*stg[NTILE+nl] + ssg4[s]*acc[i][j][e], 0.f);
                    #pragma unroll
                    for (int d = 0; d < RT; d++)
                        part[s][d] += stg[(2+d)*NTILE + nl] * hv;
                }
    }

    // cross-lane (l) reduce, then cross-warp via smem atomics
    #pragma unroll
    for (int s = 0; s < 4; s++)
        #pragma unroll
        for (int d = 0; d < RT; d++){
            float v = part[s][d];
            v += __shfl_xor_sync(0xffffffffu, v, 1);
            v += __shfl_xor_sync(0xffffffffu, v, 2);
            part[s][d] = v;
        }
    if (l == 0){
        #pragma unroll
        for (int s = 0; s < 4; s++){
            int rl = wm*32 + (s>>1)*16 + g + (s&1)*8;
            #pragma unroll
            for (int d = 0; d < RT; d++)
                if (d < R) atomicAdd(&red[rl*4 + d], part[s][d]);
        }
    }
    __syncthreads();
    if (WMODE == 0){
        if (tid < 128)
            for (int d = 0; d < R; d++)
                outp[(long)(m0 + tid)*ostride + ooff + d] = red[tid*4 + d];
    } else {
        if (tid < 32){
            float lg0 = red[(tid*4+0)*4], lg1 = red[(tid*4+1)*4];
            float lg2 = red[(tid*4+2)*4], lg3 = red[(tid*4+3)*4];
            float m = fmaxf(fmaxf(lg0,lg1), fmaxf(lg2,lg3));
            float e0 = expf(lg0-m), e1 = expf(lg1-m), e2 = expf(lg2-m), e3 = expf(lg3-m);
            float inv = 1.f/(e0+e1+e2+e3);
            outp[m0 + tid*4 + 0] = e0*inv; outp[m0 + tid*4 + 1] = e1*inv;
            outp[m0 + tid*4 + 2] = e2*inv; outp[m0 + tid*4 + 3] = e3*inv;
        }
    }
}

// ---------------- convert kernel: fp32 -> hi/lo bf16 planes ----------------
struct CvtArgs { const float *eps, *x, *w[6]; };  // w: wg, f0..f3, mu is w[5]... see below
// W plane row map: 0..63 wg | 64+i*720 fitter i | 2944..3007 mu | 3008..3071 sg
struct CvtW { const float *wg, *f0, *f1, *f2, *f3, *mu, *sg; };

#define C_EPS (NEPS/4)
#define C_X   (NX/4)
#define C_W   (NW1/4)

__global__ void convert_k(const float* __restrict__ eps, const float* __restrict__ x, CvtW w)
{
    long i = (long)blockIdx.x*256 + threadIdx.x;
    const float4* src;
    __nv_bfloat16 *dh, *dl;
    long base;
    if (i < C_EPS){
        src = (const float4*)eps + i; dh = g_eh; dl = g_el; base = i;
    } else if (i < C_EPS + C_X){
        long j = i - C_EPS;
        src = (const float4*)x + j; dh = g_xh; dl = g_xl; base = j;
    } else if (i < C_EPS + C_X + C_W){
        long j = i - C_EPS - C_X;
        int r = (int)(j/84), cc = (int)(j%84);
        const float* ws; int row;
        if (r < 64){ ws = w.wg; row = r; }
        else if (r < 2944){
            int fi = (r-64)/720; row = (r-64) - fi*720;
            ws = (fi==0)? w.f0 : (fi==1)? w.f1 : (fi==2)? w.f2 : w.f3;
        }
        else if (r < 3008){ ws = w.mu; row = r - 2944; }
        else { ws = w.sg; row = r - 3008; }
        src = (const float4*)(ws + (long)row*Tc) + cc;
        dh = g_wh; dl = g_wl; base = j;
    } else return;
    float4 v = *src;
    uint2 h, lo; cvt_split(v, h, lo);
    *(uint2*)(dh + base*4) = h;
    *(uint2*)(dl + base*4) = lo;
}

// ---------------- kernels ----------------
struct MainArgs {
    const float *wgb1, *wgW2, *Sp, *spm, *sps;
    const float *fb1[4], *fW2[4];
    float *gw, *cf;
};

__global__ __launch_bounds__(NTHR,1) void main_k(MainArgs a)
{
    extern __shared__ char smem[];
    int bid = blockIdx.x;
    if (bid < 512){   // fitters first: heavy CTAs start in wave 1
        int i  = bid >> 7;
        int m0 = (bid & 127)*128;
        int R   = (i == 2) ? 3 : ((i == 1) ? 2 : 1);
        int off = (i == 0) ? 0 : (i == 1) ? 1 : (i == 2) ? 3 : 6;
        gemm_core<128,3,0>(g_eh + i*Tc, g_el + i*Tc, 4*Tc,
                           g_wh + (64 + i*Fc)*Tc, g_wl + (64 + i*Fc)*Tc, Fc, 6,
                           a.fb1[i], a.Sp + 64 + i*Fc, a.spm, a.sps, 4, i,
                           a.fW2[i], R, a.cf, 8, off, m0, smem);
    } else {
        int m0 = (bid - 512)*128;
        gemm_core<64,1,1>(g_eh, g_el, Tc,
                          g_wh, g_wl, 64, 1,
                          a.wgb1, a.Sp, a.spm, a.sps, 1, 0,
                          a.wgW2, 1, a.gw, 1, 0, m0, smem);
    }
}

__global__ __launch_bounds__(NTHR,1) void musig_k(
    const float* mub1, const float* muW2,
    const float* sgb1, const float* sgW2, float* ms)
{
    extern __shared__ char smem[];
    if (blockIdx.y == 0)
        gemm_core<64,4,0>(g_xh, g_xl, Tc, g_wh + 2944*Tc, g_wl + 2944*Tc, 64, 1,
                          mub1, nullptr, nullptr, nullptr, 0, 0,
                          muW2, 4, ms, 8, 0, blockIdx.x*128, smem);
    else
        gemm_core<64,4,0>(g_xh, g_xl, Tc, g_wh + 3008*Tc, g_wl + 3008*Tc, 64, 1,
                          sgb1, nullptr, nullptr, nullptr, 0, 0,
                          sgW2, 4, ms, 8, 4, blockIdx.x*128, smem);
}

struct RowArgs { const float *wg, *f[4]; };
__global__ void rowsum_all(RowArgs ra, float* __restrict__ S)
{
    int r = (blockIdx.x * blockDim.x + threadIdx.x) >> 5;
    int lane = threadIdx.x & 31;
    if (r >= 64 + 4*Fc) return;
    const float* row;
    if (r < 64) row = ra.wg + (long)r*Tc;
    else { int i = (r-64)/Fc, rr = (r-64) - i*Fc; row = ra.f[i] + (long)rr*Tc; }
    float s = 0.f;
    for (int j = lane; j < Tc; j += 32) s += row[j];
    #pragma unroll
    for (int o = 16; o; o >>= 1) s += __shfl_xor_sync(0xffffffffu, s, o);
    if (lane == 0) S[r] = s;
}

__global__ void softplus_k(const float* __restrict__ mub2, const float* __restrict__ sgb2){
    int i = blockIdx.x*256 + threadIdx.x;
    if (i >= BNT*4) return;
    int row = i >> 2, k = i & 3;
    g_spmu[i] = softplus_f(g_ms[row*8 + k]     + mub2[k]);
    g_spsg[i] = softplus_f(g_ms[row*8 + 4 + k] + sgb2[k]);
}

#define FCHUNK 48
__global__ void final_kernel(float* __restrict__ out,
                             const float* __restrict__ b2_0, const float* __restrict__ b2_1,
                             const float* __restrict__ b2_2, const float* __restrict__ b2_3){
    int b  = blockIdx.y;
    int f0 = blockIdx.x * FCHUNK;
    int n  = threadIdx.x;
    int bn = b * Nch + n;
    float w0 = g_w[bn*4+0], w1 = g_w[bn*4+1], w2 = g_w[bn*4+2], w3 = g_w[bn*4+3];
    float c0 = g_coef[bn*8+0] + b2_0[0];
    float c1 = g_coef[bn*8+1] + b2_1[0], c2 = g_coef[bn*8+2] + b2_1[1];
    float c3 = g_coef[bn*8+3] + b2_2[0], c4 = g_coef[bn*8+4] + b2_2[1], c5 = g_coef[bn*8+5] + b2_2[2];
    float c6 = g_coef[bn*8+6] + b2_3[0];
    #pragma unroll 4
    for (int fi = 0; fi < FCHUNK; fi++) {
        int f = f0 + fi;
        float tt = (float)f * (1.f/719.f);
        float t2 = tt*tt, t3 = t2*tt;
        float p0 = c0 + 0.5f*tt;
        float p1 = c1 + c2*tt + 0.5f*t2;
        float p2 = c3 + c4*tt + c5*t2 + 0.5f*t3;
        float p3 = c6 - 0.5f*tt;
        out[((long)b*Fc + f)*Nch + n] = w0*p0 + w1*p1 + w2*p2 + w3*p3;
    }
}

// ---------------- launch ----------------
extern "C" void kernel_launch(void* const* d_in, const int* in_sizes, int n_in,
                              void* d_out, int out_size)
{
    const float* x     = (const float*)d_in[0];
    const float* eps   = (const float*)d_in[1];
    const float* muW1  = (const float*)d_in[2];
    const float* mub1  = (const float*)d_in[3];
    const float* muW2  = (const float*)d_in[4];
    const float* mub2  = (const float*)d_in[5];
    const float* sgW1  = (const float*)d_in[6];
    const float* sgb1  = (const float*)d_in[7];
    const float* sgW2  = (const float*)d_in[8];
    const float* sgb2  = (const float*)d_in[9];
    const float* wgW1  = (const float*)d_in[10];
    const float* wgb1  = (const float*)d_in[11];
    const float* wgW2  = (const float*)d_in[12];
    // d_in[13] = wgb2 (cancels in softmax)
    const float* fb2[4] = {(const float*)d_in[17], (const float*)d_in[21],
                           (const float*)d_in[25], (const float*)d_in[29]};
    float* out = (float*)d_out;

    float* ms;  cudaGetSymbolAddress((void**)&ms,  g_ms);
    float* spm; cudaGetSymbolAddress((void**)&spm, g_spmu);
    float* sps; cudaGetSymbolAddress((void**)&sps, g_spsg);
    float* gw;  cudaGetSymbolAddress((void**)&gw,  g_w);
    float* cf;  cudaGetSymbolAddress((void**)&cf,  g_coef);
    float* Sp;  cudaGetSymbolAddress((void**)&Sp,  g_S);

    MainArgs a;
    a.wgb1 = wgb1; a.wgW2 = wgW2;
    a.Sp = Sp; a.spm = spm; a.sps = sps; a.gw = gw; a.cf = cf;
    const float* fW1[4] = {(const float*)d_in[14], (const float*)d_in[18],
                           (const float*)d_in[22], (const float*)d_in[26]};
    a.fb1[0] = (const float*)d_in[15]; a.fW2[0] = (const float*)d_in[16];
    a.fb1[1] = (const float*)d_in[19]; a.fW2[1] = (const float*)d_in[20];
    a.fb1[2] = (const float*)d_in[23]; a.fW2[2] = (const float*)d_in[24];
    a.fb1[3] = (const float*)d_in[27]; a.fW2[3] = (const float*)d_in[28];

    RowArgs ra;
    ra.wg = wgW1;
    for (int i = 0; i < 4; i++) ra.f[i] = fW1[i];

    CvtW cw;
    cw.wg = wgW1; cw.f0 = fW1[0]; cw.f1 = fW1[1]; cw.f2 = fW1[2]; cw.f3 = fW1[3];
    cw.mu = muW1; cw.sg = sgW1;

    // smem: NT=128/RT=3: 3*57344 + 5*128*4 + 2048 = 176640
    //       NT=64 /RT=4: 3*43008 + 6*64*4 + 2048 = 132608
    const int SMEM_MAIN  = 176640;
    const int SMEM_MUSIG = 132608;
    static bool attr_set = false;
    if (!attr_set){
        cudaFuncSetAttribute(main_k,  cudaFuncAttributeMaxDynamicSharedMemorySize, SMEM_MAIN);
        cudaFuncSetAttribute(musig_k, cudaFuncAttributeMaxDynamicSharedMemorySize, SMEM_MUSIG);
        attr_set = true;
    }

    // pre-split fp32 -> hi/lo bf16 planes
    {
        long total = C_EPS + C_X + C_W;
        convert_k<<<(int)((total + 255)/256), 256>>>(eps, x, cw);
    }

    // rowsums (all 2944 rows in one launch)
    rowsum_all<<<(2944*32 + 255)/256, 256>>>(ra, Sp);

    // mu / sigma second-layer raw sums
    {
        dim3 grid(BNT/128, 2);
        musig_k<<<grid, NTHR, SMEM_MUSIG>>>(mub1, muW2, sgb1, sgW2, ms);
    }
    softplus_k<<<(BNT*4 + 255)/256, 256>>>(mub2, sgb2);

    // fitters (512 CTAs, first) + wg (512 CTAs) in one launch
    main_k<<<1024, NTHR, SMEM_MAIN>>>(a);

    // final mixture + transpose
    {
        dim3 grid(Fc/FCHUNK, Bc);
        final_kernel<<<grid, 128>>>(out, fb2[0], fb2[1], fb2[2], fb2[3]);
    }
}

// round 14
// speedup vs baseline: 1.6749x; 1.6749x over previous
#include <cuda_runtime.h>
#include <cuda_fp16.h>
#include <math.h>
#include <stdint.h>

#define Tc   336
#define BNT  16384
#define Fc   720
#define Nch  128
#define Bc   128
#define KC   48          // k-cols per smem stage
#define NSTG 7           // 336/48
#define RSTR 112         // smem row stride bytes (48 fp16 = 96B + 16 pad; 112/16=7 coprime 8)
#define NTHR 512

// ---------------- scratch globals ----------------
__device__ float g_ms[BNT*8];
__device__ float g_spmu[BNT*4];
__device__ float g_spsg[BNT*4];
__device__ float g_w[BNT*4];
__device__ float g_coef[BNT*8];
__device__ float g_S[64 + 4*Fc];

__device__ __forceinline__ float softplus_f(float x){
    return fmaxf(x,0.f) + log1pf(expf(-fabsf(x)));
}
__device__ __forceinline__ uint32_t su32(const void* p){
    uint32_t a;
    asm("{ .reg .u64 t; cvta.to.shared.u64 t, %1; cvt.u32.u64 %0, t; }" : "=r"(a) : "l"(p));
    return a;
}

#define LDSM4(r, a) asm volatile( \
    "ldmatrix.sync.aligned.m8n8.x4.shared.b16 {%0,%1,%2,%3}, [%4];" \
    : "=r"((r)[0]), "=r"((r)[1]), "=r"((r)[2]), "=r"((r)[3]) : "r"(a))
#define MMAH(c, a, b) asm volatile( \
    "mma.sync.aligned.m16n8k16.row.col.f32.f16.f16.f32 " \
    "{%0,%1,%2,%3}, {%4,%5,%6,%7}, {%8,%9}, {%0,%1,%2,%3};" \
    : "+f"((c)[0]), "+f"((c)[1]), "+f"((c)[2]), "+f"((c)[3]) \
    : "r"((a)[0]), "r"((a)[1]), "r"((a)[2]), "r"((a)[3]), "r"((b)[0]), "r"((b)[1]))

__device__ __forceinline__ uint2 cvt_h4(float4 v){
    __half2 a = __floats2half2_rn(v.x, v.y);
    __half2 b = __floats2half2_rn(v.z, v.w);
    return make_uint2(*(uint32_t*)&a, *(uint32_t*)&b);
}

// =====================================================================
// 512-thread (16-warp, 4x4 grid) double-buffered fp16 mma.sync GEMM
// with fused reduce epilogue. Single fp16 product (no hi/lo split).
//   acc[m,n] = A[m,:].W1[n,:]  (K=336)
//   h = relu(b1[n] + smu[m]*S[n] + ssg[m]*acc)
//   WMODE 0: out[m*ostride+ooff+d] = sum_n h*W2[d,n]
//   WMODE 1: logits -> softmax over groups of 4 rows -> out (g_w)
// =====================================================================
template<int NTILE, int RT, int WMODE>
__device__ __forceinline__ void gemm_core(
    const float* __restrict__ A, int lda,
    const float* __restrict__ W1, int Ncols, int n_nt,
    const float* __restrict__ b1, const float* __restrict__ S,
    const float* __restrict__ spmu, const float* __restrict__ spsg,
    int sp_mul, int sp_add,
    const float* __restrict__ W2, int R,
    float* __restrict__ outp, int ostride, int ooff,
    int m0, char* smem)
{
    constexpr int ATILE = 128*RSTR;            // 14336 bytes (fp16 A tile)
    constexpr int BTILE = NTILE*RSTR;
    constexpr int BUFSZ = ATILE + BTILE;
    constexpr int NB4   = (NTILE*12 + NTHR-1)/NTHR;  // B float4 per thread per stage
    constexpr bool BGUARD = (NTILE*12 % NTHR) != 0;
    constexpr int NJ    = NTILE/32;            // n8 tiles per warp (4x4 grid)
    constexpr int NPW   = NTILE/4;             // N cols per warp

    const int tid = threadIdx.x;
    const int wid = tid >> 5, lane = tid & 31;
    const int g = lane >> 2, l = lane & 3;
    const int wm = wid >> 2, wn = wid & 3;     // 4x4 warp grid; warp tile 32 x NPW
    const uint32_t sb = su32(smem);
    float* stg = (float*)(smem + 2*BUFSZ);
    float* red = (float*)(smem + 2*BUFSZ + (2+RT)*NTILE*4);

    if (tid < 128) ((float4*)red)[tid] = make_float4(0.f,0.f,0.f,0.f);

    float part[4][RT];
    #pragma unroll
    for (int s = 0; s < 4; s++)
        #pragma unroll
        for (int d = 0; d < RT; d++) part[s][d] = 0.f;

    float4 pa[3], pb[NB4];

    auto ldgA = [&](int kc){
        #pragma unroll
        for (int it = 0; it < 3; it++){
            int q = tid + it*NTHR; int r = q/12, cq = q - r*12;
            pa[it] = *(const float4*)(A + (long)(m0 + r)*lda + kc*KC + cq*4);
        }
    };
    auto ldgB = [&](int nt, int kc){
        #pragma unroll
        for (int it = 0; it < NB4; it++){
            int q = tid + it*NTHR;
            if (!BGUARD || q < NTILE*12){
                int n = q/12, cq = q - n*12;
                int gn = nt*NTILE + n;
                pb[it] = (gn < Ncols) ? *(const float4*)(W1 + (long)gn*Tc + kc*KC + cq*4)
                                      : make_float4(0.f,0.f,0.f,0.f);
            }
        }
    };
    auto sts = [&](int buf){
        char* bb = smem + buf*BUFSZ;
        #pragma unroll
        for (int it = 0; it < 3; it++){
            int q = tid + it*NTHR; int r = q/12, cq = q - r*12;
            *(uint2*)(bb + r*RSTR + cq*8) = cvt_h4(pa[it]);
        }
        #pragma unroll
        for (int it = 0; it < NB4; it++){
            int q = tid + it*NTHR;
            if (!BGUARD || q < NTILE*12){
                int n = q/12, cq = q - n*12;
                *(uint2*)(bb + ATILE + n*RSTR + cq*8) = cvt_h4(pb[it]);
            }
        }
    };

    for (int nt = 0; nt < n_nt; nt++){
        __syncthreads();   // stg reuse + buf0 reuse safety
        // staging: b1 / S / W2 rows for this n-tile
        for (int idx = tid; idx < NTILE*(2+RT); idx += NTHR){
            int n = idx % NTILE, row = idx / NTILE;
            int gn = nt*NTILE + n;
            float v = 0.f;
            if (gn < Ncols){
                if (row == 0)           v = b1[gn];
                else if (row == 1)      v = (S != nullptr) ? S[gn] : 0.f;
                else if (row - 2 < R)   v = W2[(row-2)*Ncols + gn];
            }
            stg[row*NTILE + n] = v;
        }

        float acc[2][NJ][4];
        #pragma unroll
        for (int i = 0; i < 2; i++)
            #pragma unroll
            for (int j = 0; j < NJ; j++)
                #pragma unroll
                for (int e = 0; e < 4; e++) acc[i][j][e] = 0.f;

        ldgA(0); ldgB(nt, 0);
        sts(0);
        __syncthreads();

        // one MMA k-step (k16) over the given buffer
        auto mma_step = [&](uint32_t base, int ks){
            uint32_t ah[2][4];
            #pragma unroll
            for (int i = 0; i < 2; i++){
                int row = wm*32 + i*16 + (lane & 15);
                uint32_t ad = base + row*RSTR + ks*32 + ((lane>>4)<<4);
                LDSM4(ah[i], ad);
            }
            uint32_t bh[NJ][2];
            #pragma unroll
            for (int p = 0; p < NJ/2; p++){
                int rowb = wn*NPW + p*16 + ((lane>>4)<<3) + (lane & 7);
                uint32_t ad = base + ATILE + rowb*RSTR + ks*32 + (((lane>>3)&1)<<4);
                uint32_t t[4];
                LDSM4(t, ad);
                bh[2*p][0]=t[0]; bh[2*p][1]=t[1]; bh[2*p+1][0]=t[2]; bh[2*p+1][1]=t[3];
            }
            #pragma unroll
            for (int i = 0; i < 2; i++)
                #pragma unroll
                for (int j = 0; j < NJ; j++)
                    MMAH(acc[i][j], ah[i], bh[j]);
        };

        for (int kc = 0; kc < NSTG; kc++){
            const uint32_t base = sb + (kc & 1)*BUFSZ;
            const bool more = (kc + 1 < NSTG);
            if (more){ ldgA(kc+1); ldgB(nt, kc+1); }
            mma_step(base, 0);
            mma_step(base, 1);
            if (more) sts((kc+1) & 1);   // STS next buffer between MMA k-steps
            mma_step(base, 2);
            __syncthreads();
        }

        // ---- epilogue: relu + affine + partial n-reduction ----
        float smu4[4], ssg4[4];
        #pragma unroll
        for (int s = 0; s < 4; s++){
            if (spmu != nullptr){
                int row = m0 + wm*32 + (s>>1)*16 + g + (s&1)*8;
                smu4[s] = spmu[row*sp_mul + sp_add];
                ssg4[s] = spsg[row*sp_mul + sp_add];
            } else { smu4[s] = 0.f; ssg4[s] = 1.f; }
        }
        #pragma unroll
        for (int i = 0; i < 2; i++)
            #pragma unroll
            for (int j = 0; j < NJ; j++)
                #pragma unroll
                for (int e = 0; e < 4; e++){
                    int nl = wn*NPW + j*8 + 2*l + (e&1);
                    int s  = i*2 + (e>>1);
                    float hv = fmaxf(stg[nl] + smu4[s]*stg[NTILE+nl] + ssg4[s]*acc[i][j][e], 0.f);
                    #pragma unroll
                    for (int d = 0; d < RT; d++)
                        part[s][d] += stg[(2+d)*NTILE + nl] * hv;
                }
    }

    // cross-lane (l) reduce, then cross-warp via smem atomics
    #pragma unroll
    for (int s = 0; s < 4; s++)
        #pragma unroll
        for (int d = 0; d < RT; d++){
            float v = part[s][d];
            v += __shfl_xor_sync(0xffffffffu, v, 1);
            v += __shfl_xor_sync(0xffffffffu, v, 2);
            part[s][d] = v;
        }
    if (l == 0){
        #pragma unroll
        for (int s = 0; s < 4; s++){
            int rl = wm*32 + (s>>1)*16 + g + (s&1)*8;
            #pragma unroll
            for (int d = 0; d < RT; d++)
                if (d < R) atomicAdd(&red[rl*4 + d], part[s][d]);
        }
    }
    __syncthreads();
    if (WMODE == 0){
        if (tid < 128)
            for (int d = 0; d < R; d++)
                outp[(long)(m0 + tid)*ostride + ooff + d] = red[tid*4 + d];
    } else {
        if (tid < 32){
            float lg0 = red[(tid*4+0)*4], lg1 = red[(tid*4+1)*4];
            float lg2 = red[(tid*4+2)*4], lg3 = red[(tid*4+3)*4];
            float m = fmaxf(fmaxf(lg0,lg1), fmaxf(lg2,lg3));
            float e0 = expf(lg0-m), e1 = expf(lg1-m), e2 = expf(lg2-m), e3 = expf(lg3-m);
            float inv = 1.f/(e0+e1+e2+e3);
            outp[m0 + tid*4 + 0] = e0*inv; outp[m0 + tid*4 + 1] = e1*inv;
            outp[m0 + tid*4 + 2] = e2*inv; outp[m0 + tid*4 + 3] = e3*inv;
        }
    }
}

// ---------------- kernels ----------------
struct MainArgs {
    const float *wgW1, *wgb1, *wgW2, *Sp, *spm, *sps;
    const float *fW1[4], *fb1[4], *fW2[4];
    float *gw, *cf;
};

__global__ __launch_bounds__(NTHR,1) void main_k(const float* __restrict__ eps, MainArgs a)
{
    extern __shared__ char smem[];
    int bid = blockIdx.x;
    if (bid < 512){   // fitters first: heavy CTAs start in wave 1
        int i  = bid >> 7;
        int m0 = (bid & 127)*128;
        int R   = (i == 2) ? 3 : ((i == 1) ? 2 : 1);
        int off = (i == 0) ? 0 : (i == 1) ? 1 : (i == 2) ? 3 : 6;
        gemm_core<128,3,0>(eps + i*Tc, 4*Tc, a.fW1[i], Fc, 6, a.fb1[i],
                           a.Sp + 64 + i*Fc, a.spm, a.sps, 4, i,
                           a.fW2[i], R, a.cf, 8, off, m0, smem);
    } else {
        int m0 = (bid - 512)*128;
        gemm_core<64,1,1>(eps, Tc, a.wgW1, 64, 1, a.wgb1, a.Sp,
                          a.spm, a.sps, 1, 0, a.wgW2, 1,
                          a.gw, 1, 0, m0, smem);
    }
}

__global__ __launch_bounds__(NTHR,1) void musig_k(
    const float* __restrict__ x,
    const float* muW1, const float* mub1, const float* muW2,
    const float* sgW1, const float* sgb1, const float* sgW2, float* ms)
{
    extern __shared__ char smem[];
    if (blockIdx.y == 0)
        gemm_core<64,4,0>(x, Tc, muW1, 64, 1, mub1, nullptr, nullptr, nullptr, 0, 0,
                          muW2, 4, ms, 8, 0, blockIdx.x*128, smem);
    else
        gemm_core<64,4,0>(x, Tc, sgW1, 64, 1, sgb1, nullptr, nullptr, nullptr, 0, 0,
                          sgW2, 4, ms, 8, 4, blockIdx.x*128, smem);
}

struct RowArgs { const float *wg, *f[4]; };
__global__ void rowsum_all(RowArgs ra, float* __restrict__ S)
{
    int r = (blockIdx.x * blockDim.x + threadIdx.x) >> 5;
    int lane = threadIdx.x & 31;
    if (r >= 64 + 4*Fc) return;
    const float* row;
    if (r < 64) row = ra.wg + (long)r*Tc;
    else { int i = (r-64)/Fc, rr = (r-64) - i*Fc; row = ra.f[i] + (long)rr*Tc; }
    float s = 0.f;
    for (int j = lane; j < Tc; j += 32) s += row[j];
    #pragma unroll
    for (int o = 16; o; o >>= 1) s += __shfl_xor_sync(0xffffffffu, s, o);
    if (lane == 0) S[r] = s;
}

__global__ void softplus_k(const float* __restrict__ mub2, const float* __restrict__ sgb2){
    int i = blockIdx.x*256 + threadIdx.x;
    if (i >= BNT*4) return;
    int row = i >> 2, k = i & 3;
    g_spmu[i] = softplus_f(g_ms[row*8 + k]     + mub2[k]);
    g_spsg[i] = softplus_f(g_ms[row*8 + 4 + k] + sgb2[k]);
}

#define FCHUNK 48
__global__ void final_kernel(float* __restrict__ out,
                             const float* __restrict__ b2_0, const float* __restrict__ b2_1,
                             const float* __restrict__ b2_2, const float* __restrict__ b2_3){
    int b  = blockIdx.y;
    int f0 = blockIdx.x * FCHUNK;
    int n  = threadIdx.x;
    int bn = b * Nch + n;
    float w0 = g_w[bn*4+0], w1 = g_w[bn*4+1], w2 = g_w[bn*4+2], w3 = g_w[bn*4+3];
    float c0 = g_coef[bn*8+0] + b2_0[0];
    float c1 = g_coef[bn*8+1] + b2_1[0], c2 = g_coef[bn*8+2] + b2_1[1];
    float c3 = g_coef[bn*8+3] + b2_2[0], c4 = g_coef[bn*8+4] + b2_2[1], c5 = g_coef[bn*8+5] + b2_2[2];
    float c6 = g_coef[bn*8+6] + b2_3[0];
    #pragma unroll 4
    for (int fi = 0; fi < FCHUNK; fi++) {
        int f = f0 + fi;
        float tt = (float)f * (1.f/719.f);
        float t2 = tt*tt, t3 = t2*tt;
        float p0 = c0 + 0.5f*tt;
        float p1 = c1 + c2*tt + 0.5f*t2;
        float p2 = c3 + c4*tt + c5*t2 + 0.5f*t3;
        float p3 = c6 - 0.5f*tt;
        out[((long)b*Fc + f)*Nch + n] = w0*p0 + w1*p1 + w2*p2 + w3*p3;
    }
}

// ---------------- launch ----------------
extern "C" void kernel_launch(void* const* d_in, const int* in_sizes, int n_in,
                              void* d_out, int out_size)
{
    const float* x     = (const float*)d_in[0];
    const float* eps   = (const float*)d_in[1];
    const float* muW1  = (const float*)d_in[2];
    const float* mub1  = (const float*)d_in[3];
    const float* muW2  = (const float*)d_in[4];
    const float* mub2  = (const float*)d_in[5];
    const float* sgW1  = (const float*)d_in[6];
    const float* sgb1  = (const float*)d_in[7];
    const float* sgW2  = (const float*)d_in[8];
    const float* sgb2  = (const float*)d_in[9];
    const float* wgW1  = (const float*)d_in[10];
    const float* wgb1  = (const float*)d_in[11];
    const float* wgW2  = (const float*)d_in[12];
    // d_in[13] = wgb2 (cancels in softmax)
    const float* fb2[4] = {(const float*)d_in[17], (const float*)d_in[21],
                           (const float*)d_in[25], (const float*)d_in[29]};
    float* out = (float*)d_out;

    float* ms;  cudaGetSymbolAddress((void**)&ms,  g_ms);
    float* spm; cudaGetSymbolAddress((void**)&spm, g_spmu);
    float* sps; cudaGetSymbolAddress((void**)&sps, g_spsg);
    float* gw;  cudaGetSymbolAddress((void**)&gw,  g_w);
    float* cf;  cudaGetSymbolAddress((void**)&cf,  g_coef);
    float* Sp;  cudaGetSymbolAddress((void**)&Sp,  g_S);

    MainArgs a;
    a.wgW1 = wgW1; a.wgb1 = wgb1; a.wgW2 = wgW2;
    a.Sp = Sp; a.spm = spm; a.sps = sps; a.gw = gw; a.cf = cf;
    a.fW1[0] = (const float*)d_in[14]; a.fb1[0] = (const float*)d_in[15]; a.fW2[0] = (const float*)d_in[16];
    a.fW1[1] = (const float*)d_in[18]; a.fb1[1] = (const float*)d_in[19]; a.fW2[1] = (const float*)d_in[20];
    a.fW1[2] = (const float*)d_in[22]; a.fb1[2] = (const float*)d_in[23]; a.fW2[2] = (const float*)d_in[24];
    a.fW1[3] = (const float*)d_in[26]; a.fb1[3] = (const float*)d_in[27]; a.fW2[3] = (const float*)d_in[28];

    RowArgs ra;
    ra.wg = wgW1;
    for (int i = 0; i < 4; i++) ra.f[i] = a.fW1[i];

    // smem: NT=128/RT=3: 2*(14336+14336) + 5*128*4 + 2048 = 61952
    //       NT=64 /RT=4: 2*(14336+7168)  + 6*64*4  + 2048 = 46592
    const int SMEM_MAIN  = 61952;
    const int SMEM_MUSIG = 46592;
    static bool attr_set = false;
    if (!attr_set){
        cudaFuncSetAttribute(main_k,  cudaFuncAttributeMaxDynamicSharedMemorySize, SMEM_MAIN);
        cudaFuncSetAttribute(musig_k, cudaFuncAttributeMaxDynamicSharedMemorySize, SMEM_MUSIG);
        attr_set = true;
    }

    // rowsums (all 2944 rows in one launch)
    rowsum_all<<<(2944*32 + 255)/256, 256>>>(ra, Sp);

    // mu / sigma second-layer raw sums
    {
        dim3 grid(BNT/128, 2);
        musig_k<<<grid, NTHR, SMEM_MUSIG>>>(x, muW1, mub1, muW2, sgW1, sgb1, sgW2, ms);
    }
    softplus_k<<<(BNT*4 + 255)/256, 256>>>(mub2, sgb2);

    // fitters (512 CTAs, first) + wg (512 CTAs) in one launch
    main_k<<<1024, NTHR, SMEM_MAIN>>>(eps, a);

    // final mixture + transpose
    {
        dim3 grid(Fc/FCHUNK, Bc);
        final_kernel<<<grid, 128>>>(out, fb2[0], fb2[1], fb2[2], fb2[3]);
    }
}

// round 15
// speedup vs baseline: 1.6846x; 1.0057x over previous
#include <cuda_runtime.h>
#include <cuda_fp16.h>
#include <math.h>
#include <stdint.h>

#define Tc   336
#define BNT  16384
#define Fc   720
#define Nch  128
#define Bc   128
#define KC   48          // k-cols per smem stage
#define NSTG 7           // 336/48
#define RSTR 112         // smem row stride bytes (48 fp16 = 96B + 16 pad; 112/16=7 coprime 8)
#define NTHR 256

// ---------------- scratch globals ----------------
__device__ float g_ms[BNT*8];
__device__ float g_spmu[BNT*4];
__device__ float g_spsg[BNT*4];
__device__ float g_w[BNT*4];
__device__ float g_coef[BNT*8];
__device__ float g_S[64 + 4*Fc];

__device__ __forceinline__ float softplus_f(float x){
    return fmaxf(x,0.f) + log1pf(expf(-fabsf(x)));
}
__device__ __forceinline__ uint32_t su32(const void* p){
    uint32_t a;
    asm("{ .reg .u64 t; cvta.to.shared.u64 t, %1; cvt.u32.u64 %0, t; }" : "=r"(a) : "l"(p));
    return a;
}

#define LDSM4(r, a) asm volatile( \
    "ldmatrix.sync.aligned.m8n8.x4.shared.b16 {%0,%1,%2,%3}, [%4];" \
    : "=r"((r)[0]), "=r"((r)[1]), "=r"((r)[2]), "=r"((r)[3]) : "r"(a))
#define MMAH(c, a, b) asm volatile( \
    "mma.sync.aligned.m16n8k16.row.col.f32.f16.f16.f32 " \
    "{%0,%1,%2,%3}, {%4,%5,%6,%7}, {%8,%9}, {%0,%1,%2,%3};" \
    : "+f"((c)[0]), "+f"((c)[1]), "+f"((c)[2]), "+f"((c)[3]) \
    : "r"((a)[0]), "r"((a)[1]), "r"((a)[2]), "r"((a)[3]), "r"((b)[0]), "r"((b)[1]))

__device__ __forceinline__ uint2 cvt_h4(float4 v){
    __half2 a = __floats2half2_rn(v.x, v.y);
    __half2 b = __floats2half2_rn(v.z, v.w);
    return make_uint2(*(uint32_t*)&a, *(uint32_t*)&b);
}

// =====================================================================
// 256-thread (8-warp, 2x4 grid, 64x64 warp tile) double-buffered fp16
// mma.sync GEMM with fused reduce epilogue.
//   acc[m,n] = A[m,:].W1[n,:]  (K=336)
//   h = relu(b1[n] + smu[m]*S[n] + ssg[m]*acc)
//   WMODE 0: out[m*ostride+ooff+d] = sum_n h*W2[d,n]
//   WMODE 1: logits -> softmax over groups of 4 rows -> out (g_w)
// =====================================================================
template<int NTILE, int RT, int WMODE>
__device__ __forceinline__ void gemm_core(
    const float* __restrict__ A, int lda,
    const float* __restrict__ W1, int Ncols, int n_nt,
    const float* __restrict__ b1, const float* __restrict__ S,
    const float* __restrict__ spmu, const float* __restrict__ spsg,
    int sp_mul, int sp_add,
    const float* __restrict__ W2, int R,
    float* __restrict__ outp, int ostride, int ooff,
    int m0, char* smem)
{
    constexpr int ATILE = 128*RSTR;                  // fp16 A tile bytes
    constexpr int BTILE = NTILE*RSTR;
    constexpr int BUFSZ = ATILE + BTILE;
    constexpr int NB4   = NTILE*12/NTHR;             // B float4 chunks per thread per stage
    constexpr int NB0   = (NB4+1)/2, NB1 = NB4-NB0;
    constexpr int NJ    = NTILE/32;                  // n8 tiles per warp
    constexpr int NPW   = NTILE/4;                   // N cols per warp

    const int tid = threadIdx.x;
    const int wid = tid >> 5, lane = tid & 31;
    const int g = lane >> 2, l = lane & 3;
    const int wm = wid >> 2, wn = wid & 3;           // 2x4 warp grid; warp tile 64 x NPW
    const uint32_t sb = su32(smem);
    float* stg = (float*)(smem + 2*BUFSZ);
    float* red = (float*)(smem + 2*BUFSZ + (2+RT)*NTILE*4);

    if (tid < 128) ((float4*)red)[tid] = make_float4(0.f,0.f,0.f,0.f);

    float part[8][RT];
    #pragma unroll
    for (int s = 0; s < 8; s++)
        #pragma unroll
        for (int d = 0; d < RT; d++) part[s][d] = 0.f;

    float4 pa[6], pb0[NB0], pb1[NB1 > 0 ? NB1 : 1];

    auto ldgA = [&](int kc){
        #pragma unroll
        for (int it = 0; it < 6; it++){
            int q = tid + it*NTHR; int r = q/12, cq = q - r*12;
            pa[it] = *(const float4*)(A + (long)(m0 + r)*lda + kc*KC + cq*4);
        }
    };
    auto stsA = [&](int buf){
        char* bb = smem + buf*BUFSZ;
        #pragma unroll
        for (int it = 0; it < 6; it++){
            int q = tid + it*NTHR; int r = q/12, cq = q - r*12;
            *(uint2*)(bb + r*RSTR + cq*8) = cvt_h4(pa[it]);
        }
    };
    auto ldgB0 = [&](int nt, int kc){
        #pragma unroll
        for (int it = 0; it < NB0; it++){
            int q = tid + it*NTHR; int n = q/12, cq = q - n*12;
            int gn = nt*NTILE + n;
            pb0[it] = (gn < Ncols) ? *(const float4*)(W1 + (long)gn*Tc + kc*KC + cq*4)
                                   : make_float4(0.f,0.f,0.f,0.f);
        }
    };
    auto stsB0 = [&](int buf){
        char* bb = smem + buf*BUFSZ + ATILE;
        #pragma unroll
        for (int it = 0; it < NB0; it++){
            int q = tid + it*NTHR; int n = q/12, cq = q - n*12;
            *(uint2*)(bb + n*RSTR + cq*8) = cvt_h4(pb0[it]);
        }
    };
    auto ldgB1 = [&](int nt, int kc){
        #pragma unroll
        for (int it = 0; it < NB1; it++){
            int q = tid + (NB0 + it)*NTHR; int n = q/12, cq = q - n*12;
            int gn = nt*NTILE + n;
            pb1[it] = (gn < Ncols) ? *(const float4*)(W1 + (long)gn*Tc + kc*KC + cq*4)
                                   : make_float4(0.f,0.f,0.f,0.f);
        }
    };
    auto stsB1 = [&](int buf){
        char* bb = smem + buf*BUFSZ + ATILE;
        #pragma unroll
        for (int it = 0; it < NB1; it++){
            int q = tid + (NB0 + it)*NTHR; int n = q/12, cq = q - n*12;
            *(uint2*)(bb + n*RSTR + cq*8) = cvt_h4(pb1[it]);
        }
    };

    for (int nt = 0; nt < n_nt; nt++){
        __syncthreads();   // stg reuse + buf0 reuse safety
        // staging: b1 / S / W2 rows for this n-tile
        for (int idx = tid; idx < NTILE*(2+RT); idx += NTHR){
            int n = idx % NTILE, row = idx / NTILE;
            int gn = nt*NTILE + n;
            float v = 0.f;
            if (gn < Ncols){
                if (row == 0)           v = b1[gn];
                else if (row == 1)      v = (S != nullptr) ? S[gn] : 0.f;
                else if (row - 2 < R)   v = W2[(row-2)*Ncols + gn];
            }
            stg[row*NTILE + n] = v;
        }

        float acc[4][NJ][4];
        #pragma unroll
        for (int i = 0; i < 4; i++)
            #pragma unroll
            for (int j = 0; j < NJ; j++)
                #pragma unroll
                for (int e = 0; e < 4; e++) acc[i][j][e] = 0.f;

        ldgA(0); stsA(0);
        ldgB0(nt, 0); stsB0(0);
        ldgB1(nt, 0); stsB1(0);
        __syncthreads();

        // one MMA k-step (k16) over the given buffer
        auto mma_step = [&](uint32_t base, int ks){
            uint32_t ah[4][4];
            #pragma unroll
            for (int i = 0; i < 4; i++){
                int row = wm*64 + i*16 + (lane & 15);
                uint32_t ad = base + row*RSTR + ks*32 + ((lane>>4)<<4);
                LDSM4(ah[i], ad);
            }
            uint32_t bh[NJ][2];
            #pragma unroll
            for (int p = 0; p < NJ/2; p++){
                int rowb = wn*NPW + p*16 + ((lane>>4)<<3) + (lane & 7);
                uint32_t ad = base + ATILE + rowb*RSTR + ks*32 + (((lane>>3)&1)<<4);
                uint32_t t[4];
                LDSM4(t, ad);
                bh[2*p][0]=t[0]; bh[2*p][1]=t[1]; bh[2*p+1][0]=t[2]; bh[2*p+1][1]=t[3];
            }
            #pragma unroll
            for (int i = 0; i < 4; i++)
                #pragma unroll
                for (int j = 0; j < NJ; j++)
                    MMAH(acc[i][j], ah[i], bh[j]);
        };

        for (int kc = 0; kc < NSTG; kc++){
            const uint32_t base = sb + (kc & 1)*BUFSZ;
            const int nb = (kc + 1) & 1;
            const bool more = (kc + 1 < NSTG);
            if (more) ldgA(kc+1);
            mma_step(base, 0);
            if (more){ stsA(nb); ldgB0(nt, kc+1); }
            mma_step(base, 1);
            if (more){ stsB0(nb); ldgB1(nt, kc+1); }
            mma_step(base, 2);
            if (more) stsB1(nb);
            __syncthreads();
        }

        // ---- epilogue: relu + affine + partial n-reduction ----
        float smu8[8], ssg8[8];
        #pragma unroll
        for (int s = 0; s < 8; s++){
            if (spmu != nullptr){
                int row = m0 + wm*64 + (s>>1)*16 + g + (s&1)*8;
                smu8[s] = spmu[row*sp_mul + sp_add];
                ssg8[s] = spsg[row*sp_mul + sp_add];
            } else { smu8[s] = 0.f; ssg8[s] = 1.f; }
        }
        #pragma unroll
        for (int i = 0; i < 4; i++)
            #pragma unroll
            for (int j = 0; j < NJ; j++)
                #pragma unroll
                for (int e = 0; e < 4; e++){
                    int nl = wn*NPW + j*8 + 2*l + (e&1);
                    int s  = i*2 + (e>>1);
                    float hv = fmaxf(stg[nl] + smu8[s]*stg[NTILE+nl] + ssg8[s]*acc[i][j][e], 0.f);
                    #pragma unroll
                    for (int d = 0; d < RT; d++)
                        part[s][d] += stg[(2+d)*NTILE + nl] * hv;
                }
    }

    // cross-lane (l) reduce, then cross-warp via smem atomics
    #pragma unroll
    for (int s = 0; s < 8; s++)
        #pragma unroll
        for (int d = 0; d < RT; d++){
            float v = part[s][d];
            v += __shfl_xor_sync(0xffffffffu, v, 1);
            v += __shfl_xor_sync(0xffffffffu, v, 2);
            part[s][d] = v;
        }
    if (l == 0){
        #pragma unroll
        for (int s = 0; s < 8; s++){
            int rl = wm*64 + (s>>1)*16 + g + (s&1)*8;
            #pragma unroll
            for (int d = 0; d < RT; d++)
                if (d < R) atomicAdd(&red[rl*4 + d], part[s][d]);
        }
    }
    __syncthreads();
    if (WMODE == 0){
        if (tid < 128)
            for (int d = 0; d < R; d++)
                outp[(long)(m0 + tid)*ostride + ooff + d] = red[tid*4 + d];
    } else {
        if (tid < 32){
            float lg0 = red[(tid*4+0)*4], lg1 = red[(tid*4+1)*4];
            float lg2 = red[(tid*4+2)*4], lg3 = red[(tid*4+3)*4];
            float m = fmaxf(fmaxf(lg0,lg1), fmaxf(lg2,lg3));
            float e0 = expf(lg0-m), e1 = expf(lg1-m), e2 = expf(lg2-m), e3 = expf(lg3-m);
            float inv = 1.f/(e0+e1+e2+e3);
            outp[m0 + tid*4 + 0] = e0*inv; outp[m0 + tid*4 + 1] = e1*inv;
            outp[m0 + tid*4 + 2] = e2*inv; outp[m0 + tid*4 + 3] = e3*inv;
        }
    }
}

// ---------------- kernels ----------------
struct MainArgs {
    const float *wgW1, *wgb1, *wgW2, *Sp, *spm, *sps;
    const float *fW1[4], *fb1[4], *fW2[4];
    float *gw, *cf;
};

__global__ __launch_bounds__(NTHR,1) void main_k(const float* __restrict__ eps, MainArgs a)
{
    extern __shared__ char smem[];
    int bid = blockIdx.x;
    if (bid < 512){   // fitters first: heavy CTAs start in wave 1
        int i  = bid >> 7;
        int m0 = (bid & 127)*128;
        int R   = (i == 2) ? 3 : ((i == 1) ? 2 : 1);
        int off = (i == 0) ? 0 : (i == 1) ? 1 : (i == 2) ? 3 : 6;
        gemm_core<256,3,0>(eps + i*Tc, 4*Tc, a.fW1[i], Fc, 3, a.fb1[i],
                           a.Sp + 64 + i*Fc, a.spm, a.sps, 4, i,
                           a.fW2[i], R, a.cf, 8, off, m0, smem);
    } else {
        int m0 = (bid - 512)*128;
        gemm_core<64,1,1>(eps, Tc, a.wgW1, 64, 1, a.wgb1, a.Sp,
                          a.spm, a.sps, 1, 0, a.wgW2, 1,
                          a.gw, 1, 0, m0, smem);
    }
}

__global__ __launch_bounds__(NTHR,1) void musig_k(
    const float* __restrict__ x,
    const float* muW1, const float* mub1, const float* muW2,
    const float* sgW1, const float* sgb1, const float* sgW2, float* ms)
{
    extern __shared__ char smem[];
    if (blockIdx.y == 0)
        gemm_core<64,4,0>(x, Tc, muW1, 64, 1, mub1, nullptr, nullptr, nullptr, 0, 0,
                          muW2, 4, ms, 8, 0, blockIdx.x*128, smem);
    else
        gemm_core<64,4,0>(x, Tc, sgW1, 64, 1, sgb1, nullptr, nullptr, nullptr, 0, 0,
                          sgW2, 4, ms, 8, 4, blockIdx.x*128, smem);
}

struct RowArgs { const float *wg, *f[4]; };
__global__ void rowsum_all(RowArgs ra, float* __restrict__ S)
{
    int r = (blockIdx.x * blockDim.x + threadIdx.x) >> 5;
    int lane = threadIdx.x & 31;
    if (r >= 64 + 4*Fc) return;
    const float* row;
    if (r < 64) row = ra.wg + (long)r*Tc;
    else { int i = (r-64)/Fc, rr = (r-64) - i*Fc; row = ra.f[i] + (long)rr*Tc; }
    float s = 0.f;
    for (int j = lane; j < Tc; j += 32) s += row[j];
    #pragma unroll
    for (int o = 16; o; o >>= 1) s += __shfl_xor_sync(0xffffffffu, s, o);
    if (lane == 0) S[r] = s;
}

__global__ void softplus_k(const float* __restrict__ mub2, const float* __restrict__ sgb2){
    int i = blockIdx.x*256 + threadIdx.x;
    if (i >= BNT*4) return;
    int row = i >> 2, k = i & 3;
    g_spmu[i] = softplus_f(g_ms[row*8 + k]     + mub2[k]);
    g_spsg[i] = softplus_f(g_ms[row*8 + 4 + k] + sgb2[k]);
}

#define FCHUNK 48
__global__ void final_kernel(float* __restrict__ out,
                             const float* __restrict__ b2_0, const float* __restrict__ b2_1,
                             const float* __restrict__ b2_2, const float* __restrict__ b2_3){
    int b  = blockIdx.y;
    int f0 = blockIdx.x * FCHUNK;
    int n  = threadIdx.x;
    int bn = b * Nch + n;
    float w0 = g_w[bn*4+0], w1 = g_w[bn*4+1], w2 = g_w[bn*4+2], w3 = g_w[bn*4+3];
    float c0 = g_coef[bn*8+0] + b2_0[0];
    float c1 = g_coef[bn*8+1] + b2_1[0], c2 = g_coef[bn*8+2] + b2_1[1];
    float c3 = g_coef[bn*8+3] + b2_2[0], c4 = g_coef[bn*8+4] + b2_2[1], c5 = g_coef[bn*8+5] + b2_2[2];
    float c6 = g_coef[bn*8+6] + b2_3[0];
    #pragma unroll 4
    for (int fi = 0; fi < FCHUNK; fi++) {
        int f = f0 + fi;
        float tt = (float)f * (1.f/719.f);
        float t2 = tt*tt, t3 = t2*tt;
        float p0 = c0 + 0.5f*tt;
        float p1 = c1 + c2*tt + 0.5f*t2;
        float p2 = c3 + c4*tt + c5*t2 + 0.5f*t3;
        float p3 = c6 - 0.5f*tt;
        out[((long)b*Fc + f)*Nch + n] = w0*p0 + w1*p1 + w2*p2 + w3*p3;
    }
}

// ---------------- launch ----------------
extern "C" void kernel_launch(void* const* d_in, const int* in_sizes, int n_in,
                              void* d_out, int out_size)
{
    const float* x     = (const float*)d_in[0];
    const float* eps   = (const float*)d_in[1];
    const float* muW1  = (const float*)d_in[2];
    const float* mub1  = (const float*)d_in[3];
    const float* muW2  = (const float*)d_in[4];
    const float* mub2  = (const float*)d_in[5];
    const float* sgW1  = (const float*)d_in[6];
    const float* sgb1  = (const float*)d_in[7];
    const float* sgW2  = (const float*)d_in[8];
    const float* sgb2  = (const float*)d_in[9];
    const float* wgW1  = (const float*)d_in[10];
    const float* wgb1  = (const float*)d_in[11];
    const float* wgW2  = (const float*)d_in[12];
    // d_in[13] = wgb2 (cancels in softmax)
    const float* fb2[4] = {(const float*)d_in[17], (const float*)d_in[21],
                           (const float*)d_in[25], (const float*)d_in[29]};
    float* out = (float*)d_out;

    float* ms;  cudaGetSymbolAddress((void**)&ms,  g_ms);
    float* spm; cudaGetSymbolAddress((void**)&spm, g_spmu);
    float* sps; cudaGetSymbolAddress((void**)&sps, g_spsg);
    float* gw;  cudaGetSymbolAddress((void**)&gw,  g_w);
    float* cf;  cudaGetSymbolAddress((void**)&cf,  g_coef);
    float* Sp;  cudaGetSymbolAddress((void**)&Sp,  g_S);

    MainArgs a;
    a.wgW1 = wgW1; a.wgb1 = wgb1; a.wgW2 = wgW2;
    a.Sp = Sp; a.spm = spm; a.sps = sps; a.gw = gw; a.cf = cf;
    a.fW1[0] = (const float*)d_in[14]; a.fb1[0] = (const float*)d_in[15]; a.fW2[0] = (const float*)d_in[16];
    a.fW1[1] = (const float*)d_in[18]; a.fb1[1] = (const float*)d_in[19]; a.fW2[1] = (const float*)d_in[20];
    a.fW1[2] = (const float*)d_in[22]; a.fb1[2] = (const float*)d_in[23]; a.fW2[2] = (const float*)d_in[24];
    a.fW1[3] = (const float*)d_in[26]; a.fb1[3] = (const float*)d_in[27]; a.fW2[3] = (const float*)d_in[28];

    RowArgs ra;
    ra.wg = wgW1;
    for (int i = 0; i < 4; i++) ra.f[i] = a.fW1[i];

    // smem: NT=256/RT=3: 2*(14336+28672) + 5*256*4 + 2048 = 93184
    //       NT=64 /RT=4: 2*(14336+7168)  + 6*64*4  + 2048 = 46592
    const int SMEM_MAIN  = 93184;
    const int SMEM_MUSIG = 46592;
    static bool attr_set = false;
    if (!attr_set){
        cudaFuncSetAttribute(main_k,  cudaFuncAttributeMaxDynamicSharedMemorySize, SMEM_MAIN);
        cudaFuncSetAttribute(musig_k, cudaFuncAttributeMaxDynamicSharedMemorySize, SMEM_MUSIG);
        attr_set = true;
    }

    // rowsums (all 2944 rows in one launch)
    rowsum_all<<<(2944*32 + 255)/256, 256>>>(ra, Sp);

    // mu / sigma second-layer raw sums
    {
        dim3 grid(BNT/128, 2);
        musig_k<<<grid, NTHR, SMEM_MUSIG>>>(x, muW1, mub1, muW2, sgW1, sgb1, sgW2, ms);
    }
    softplus_k<<<(BNT*4 + 255)/256, 256>>>(mub2, sgb2);

    // fitters (512 CTAs, first) + wg (512 CTAs) in one launch
    main_k<<<1024, NTHR, SMEM_MAIN>>>(eps, a);

    // final mixture + transpose
    {
        dim3 grid(Fc/FCHUNK, Bc);
        final_kernel<<<grid, 128>>>(out, fb2[0], fb2[1], fb2[2], fb2[3]);
    }
}